// round 9
// baseline (speedup 1.0000x reference)
#include <cuda_runtime.h>
#include <cuda_fp16.h>
#include <math.h>
#include <stdint.h>

// ---------------- problem constants ----------------
#define Hc   1024
#define Lc   4096
#define Bc   8
#define Mtok (Bc * Lc)          // 32768 tokens

typedef __half fp16;

// ---------------- scratch (device globals; no allocs allowed) ----------------
__device__ float g_gated[(size_t)Mtok * Hc];
// fp16 intermediates
__device__ fp16 g_xh[(size_t)Mtok * Hc];
__device__ fp16 g_cnnh[(size_t)Mtok * Hc];
__device__ fp16 g_xnh[(size_t)Mtok * Hc];
__device__ fp16 g_Uh[(size_t)Mtok * 3 * Hc];
__device__ fp16 g_blendh[(size_t)Mtok * Hc];
__device__ fp16 g_a1h[(size_t)Mtok * Hc];
__device__ fp16 g_t1h[(size_t)Mtok * 2 * Hc];
__device__ fp16 g_a2h[(size_t)Mtok * 2 * Hc];
// transposed fp16 weights, layout [N][K]
__device__ fp16 g_WcT[1024 * 4096];
__device__ fp16 g_WuT[3072 * 1024];
__device__ fp16 g_W1T[2048 * 1024];
__device__ fp16 g_W2T[1024 * 2048];

// ---------------- helpers ----------------
__device__ __forceinline__ float blockReduceSum(float v) {
    __shared__ float red[32];
    int lane = threadIdx.x & 31;
    int wid  = threadIdx.x >> 5;
    #pragma unroll
    for (int o = 16; o > 0; o >>= 1) v += __shfl_xor_sync(0xffffffffu, v, o);
    if (lane == 0) red[wid] = v;
    __syncthreads();
    int nw = blockDim.x >> 5;
    if (wid == 0) {
        float s = (lane < nw) ? red[lane] : 0.0f;
        #pragma unroll
        for (int o = 16; o > 0; o >>= 1) s += __shfl_xor_sync(0xffffffffu, s, o);
        if (lane == 0) red[0] = s;
    }
    __syncthreads();
    float r = red[0];
    __syncthreads();
    return r;
}

__device__ __forceinline__ float geluf(float x) {
    return 0.5f * x * (1.0f + erff(x * 0.7071067811865476f));
}

__device__ __forceinline__ uint32_t cvta_s(const void* p) {
    uint32_t a;
    asm("{ .reg .u64 t; cvta.to.shared.u64 t, %1; cvt.u32.u64 %0, t; }" : "=r"(a) : "l"(p));
    return a;
}

// ---------------- weight prep ----------------
// fp32 [K][N] row-major -> fp16 [N][K]
__global__ void wtrans_kernel(const float* __restrict__ in,
                              fp16* __restrict__ oh, int Kd, int N) {
    __shared__ float tile[32][33];
    int n0 = blockIdx.x * 32, k0 = blockIdx.y * 32;
    int tx = threadIdx.x, ty = threadIdx.y;  // 32 x 8
    #pragma unroll
    for (int i = 0; i < 32; i += 8)
        tile[ty + i][tx] = in[(size_t)(k0 + ty + i) * N + n0 + tx];
    __syncthreads();
    #pragma unroll
    for (int i = 0; i < 32; i += 8) {
        float v = tile[tx][ty + i];
        oh[(size_t)(n0 + ty + i) * Kd + k0 + tx] = __float2half(v);
    }
}

// conv weights (ho,hi,k) -> [ho][k*1024+hi]
__global__ void wconv_kernel(const float* __restrict__ w, fp16* __restrict__ oh) {
    int ho = blockIdx.x;
    for (int hi = threadIdx.x; hi < 1024; hi += 256) {
        float4 v = *reinterpret_cast<const float4*>(w + ((size_t)ho * 1024 + hi) * 4);
        float vv[4] = {v.x, v.y, v.z, v.w};
        #pragma unroll
        for (int k = 0; k < 4; k++)
            oh[(size_t)ho * 4096 + k * 1024 + hi] = __float2half(vv[k]);
    }
}

// fp32 -> fp16 elementwise
__global__ void fcvt_kernel(const float* __restrict__ in, fp16* __restrict__ oh) {
    size_t i = ((size_t)blockIdx.x * 256 + threadIdx.x) * 4;
    float4 v = *reinterpret_cast<const float4*>(in + i);
    __half2 a = __floats2half2_rn(v.x, v.y);
    __half2 b = __floats2half2_rn(v.z, v.w);
    *reinterpret_cast<__half2*>(oh + i)     = a;
    *reinterpret_cast<__half2*>(oh + i + 2) = b;
}

// ---------------- fp16 HMMA GEMM (cp.async 4-stage + ldmatrix) ----------------
// C = A @ B (+bias)(+resid); A: [M][K] fp16 (CONV=1: implicit im2col of x),
// B: [N][K] fp16. F16OUT=1: C fp16 (+bias); else f32 (+bias,+resid).
#define ROWB   80                 // padded SMEM row stride: 64B data + 16B pad
#define OPB    (128 * ROWB)       // one operand region per stage = 10240 B
#define STAGEB (2 * OPB)          // A|B = 20480 B
#define NST    4
#define SMEM_TOT (NST * STAGEB)   // 81920 B

#define MMA16816(d, a, b)                                                        \
    asm volatile("mma.sync.aligned.m16n8k16.row.col.f32.f16.f16.f32 "            \
                 "{%0,%1,%2,%3},{%4,%5,%6,%7},{%8,%9},{%0,%1,%2,%3};"            \
                 : "+f"((d)[0]), "+f"((d)[1]), "+f"((d)[2]), "+f"((d)[3])        \
                 : "r"((a)[0]), "r"((a)[1]), "r"((a)[2]), "r"((a)[3]),           \
                   "r"((b)[0]), "r"((b)[1]))

#define LDSM4(r0, r1, r2, r3, addr)                                              \
    asm volatile("ldmatrix.sync.aligned.m8n8.x4.shared.b16 {%0,%1,%2,%3}, [%4];" \
                 : "=r"(r0), "=r"(r1), "=r"(r2), "=r"(r3) : "r"(addr))

#define CPA(dst, src, sz)                                                        \
    asm volatile("cp.async.cg.shared.global [%0], [%1], 16, %2;"                 \
                 :: "r"(dst), "l"(src), "r"(sz) : "memory")

#define CPA_COMMIT() asm volatile("cp.async.commit_group;" ::: "memory")
#define CPA_WAIT2()  asm volatile("cp.async.wait_group 2;" ::: "memory")

template<int CONV, int F16OUT>
__global__ void __launch_bounds__(256, 2)
mma_gemm(const fp16* __restrict__ Ah, const fp16* __restrict__ Bh,
         void* __restrict__ Cv,
         const float* __restrict__ bias, const float* __restrict__ resid,
         int N, int Kd)
{
    extern __shared__ char sm[];
    const uint32_t sb = cvta_s(sm);
    const int tid = threadIdx.x;
    const int wid = tid >> 5, lid = tid & 31;
    const int wm = wid >> 2, wn = wid & 3;         // 2 x 4 warp grid, 64x32 warp tiles
    const int m0 = blockIdx.y * 128, n0 = blockIdx.x * 128;

    const int crow = tid >> 2, cc = tid & 3;

    const uint32_t aLane = (uint32_t)((lid & 15) * ROWB + (lid >> 4) * 16);
    const uint32_t bLane = (uint32_t)((((lid & 7) + ((lid >> 4) << 3)) * ROWB) +
                                      (((lid >> 3) & 1) * 16));

    float acc[4][4][4];
    #pragma unroll
    for (int i = 0; i < 4; i++)
        #pragma unroll
        for (int j = 0; j < 4; j++)
            #pragma unroll
            for (int q = 0; q < 4; q++) acc[i][j][q] = 0.0f;

    #define ISSUE(slot, kg)                                                          \
        {                                                                            \
            uint32_t dbase = sb + (uint32_t)(slot) * STAGEB;                         \
            _Pragma("unroll")                                                        \
            for (int p = 0; p < 2; ++p) {                                            \
                int r = crow + p * 64;                                               \
                uint32_t off = (uint32_t)(r * ROWB + cc * 16);                       \
                size_t bo = (size_t)(n0 + r) * Kd + (kg) + cc * 8;                   \
                CPA(dbase + OPB + off, Bh + bo, 16);                                 \
                if (CONV) {                                                          \
                    int kidx = (kg) >> 10;                                           \
                    bool ok = (((m0 + r) & (Lc - 1)) + kidx) >= 3;                   \
                    size_t ao = (size_t)(m0 + r + kidx - 3) * Hc +                   \
                                ((kg) & 1023) + cc * 8;                              \
                    const fp16* sh = ok ? Ah + ao : Ah;                              \
                    int sz = ok ? 16 : 0;                                            \
                    CPA(dbase + off, sh, sz);                                        \
                } else {                                                             \
                    size_t ao = (size_t)(m0 + r) * Kd + (kg) + cc * 8;               \
                    CPA(dbase + off, Ah + ao, 16);                                   \
                }                                                                    \
            }                                                                        \
        }

    const int T = Kd / 32;
    ISSUE(0, 0);  CPA_COMMIT();
    ISSUE(1, 32); CPA_COMMIT();
    ISSUE(2, 64); CPA_COMMIT();

    int slot = 0;
    for (int t = 0; t < T; ++t) {
        CPA_WAIT2();
        __syncthreads();
        if (t + 3 < T) {
            int ns = slot + 3; if (ns >= NST) ns -= NST;
            ISSUE(ns, (t + 3) * 32);
        }
        CPA_COMMIT();

        const uint32_t base = sb + (uint32_t)slot * STAGEB;
        #pragma unroll
        for (int ks = 0; ks < 2; ++ks) {
            const uint32_t ko = ks * 32;
            uint32_t ah[4][4], bh[4][2];
            #pragma unroll
            for (int i = 0; i < 4; ++i) {
                uint32_t ra = base + (uint32_t)((wm * 64 + i * 16) * ROWB) + aLane + ko;
                LDSM4(ah[i][0], ah[i][1], ah[i][2], ah[i][3], ra);
            }
            #pragma unroll
            for (int jp = 0; jp < 2; ++jp) {
                uint32_t rb = base + OPB +
                              (uint32_t)((wn * 32 + jp * 16) * ROWB) + bLane + ko;
                LDSM4(bh[2 * jp][0], bh[2 * jp][1], bh[2 * jp + 1][0], bh[2 * jp + 1][1], rb);
            }
            #pragma unroll
            for (int i = 0; i < 4; ++i)
                #pragma unroll
                for (int j = 0; j < 4; ++j)
                    MMA16816(acc[i][j], ah[i], bh[j]);
        }
        ++slot; if (slot >= NST) slot = 0;
    }

    // ---- epilogue ----
    const int g = lid >> 2, t4 = lid & 3;
    float* Cf = (float*)Cv;
    fp16*  Ch = (fp16*)Cv;
    #pragma unroll
    for (int i = 0; i < 4; ++i) {
        int r0 = m0 + wm * 64 + i * 16 + g;
        #pragma unroll
        for (int j = 0; j < 4; ++j) {
            int ccl = n0 + wn * 32 + j * 8 + 2 * t4;
            float2 v0 = make_float2(acc[i][j][0], acc[i][j][1]);
            float2 v1 = make_float2(acc[i][j][2], acc[i][j][3]);
            if (bias) {
                float2 bb = *reinterpret_cast<const float2*>(bias + ccl);
                v0.x += bb.x; v0.y += bb.y; v1.x += bb.x; v1.y += bb.y;
            }
            if (F16OUT) {
                *reinterpret_cast<__half2*>(Ch + (size_t)r0 * N + ccl) =
                    __floats2half2_rn(v0.x, v0.y);
                *reinterpret_cast<__half2*>(Ch + (size_t)(r0 + 8) * N + ccl) =
                    __floats2half2_rn(v1.x, v1.y);
            } else {
                if (resid) {
                    float2 q0 = *reinterpret_cast<const float2*>(resid + (size_t)r0 * N + ccl);
                    float2 q1 = *reinterpret_cast<const float2*>(resid + (size_t)(r0 + 8) * N + ccl);
                    v0.x += q0.x; v0.y += q0.y; v1.x += q1.x; v1.y += q1.y;
                }
                *reinterpret_cast<float2*>(Cf + (size_t)r0 * N + ccl) = v0;
                *reinterpret_cast<float2*>(Cf + (size_t)(r0 + 8) * N + ccl) = v1;
            }
        }
    }
    #undef ISSUE
}

// ---------------- layernorm over H=1024, fp16 in -> fp16 out ----------------
__global__ void ln_kernel(const fp16* __restrict__ in, fp16* __restrict__ oh,
                          const float* __restrict__ w, const float* __restrict__ b) {
    int t = blockIdx.x, tid = threadIdx.x;
    const fp16* row = in + (size_t)t * Hc;
    float v[4];
    float s = 0.0f;
    #pragma unroll
    for (int i = 0; i < 4; i++) { v[i] = __half2float(row[tid + i * 256]); s += v[i]; }
    s = blockReduceSum(s);
    float mean = s * (1.0f / Hc);
    float sq = 0.0f;
    #pragma unroll
    for (int i = 0; i < 4; i++) { float d = v[i] - mean; sq += d * d; }
    sq = blockReduceSum(sq);
    float rstd = rsqrtf(sq * (1.0f / Hc) + 1e-5f);
    #pragma unroll
    for (int i = 0; i < 4; i++) {
        int idx = tid + i * 256;
        float o = (v[i] - mean) * rstd * w[idx] + b[idx];
        oh[(size_t)t * Hc + idx] = __float2half(o);
    }
}

// ---------------- SRU scan + lambda blend (triple-buffer prefetch, depth 2 blocks) ----------------
#define UNR 8
__global__ void __launch_bounds__(32)
scan_kernel(const fp16* __restrict__ U, const fp16* __restrict__ xn,
            const fp16* __restrict__ cnn, fp16* __restrict__ blend,
            const float* __restrict__ vf_, const float* __restrict__ vr_,
            const float* __restrict__ bf_, const float* __restrict__ br_,
            const float* __restrict__ lam_, int Bv) {
    int g = blockIdx.x * 32 + threadIdx.x;
    if (g >= Bv * Hc) return;
    int b = g >> 10, h = g & 1023;
    const float vf = vf_[h], vr = vr_[h], bfv = bf_[h], brv = br_[h], lam = lam_[h];
    const float SCALE_X = sqrtf(1.0f + expf(-4.0f));
    const size_t base_u = ((size_t)b * Lc) * (3 * Hc) + h;
    const size_t base_x = ((size_t)b * Lc) * Hc + h;
    const int NB = Lc / UNR;  // 512

    float bu0[3][UNR], bu1[3][UNR], bu2[3][UNR], bxn[3][UNR], bcn[3][UNR];
    float c = 0.0f;

    #define PREF(buf, nb)                                                         \
        {                                                                         \
            size_t pu = base_u + (size_t)(nb) * UNR * (3 * Hc);                   \
            size_t px = base_x + (size_t)(nb) * UNR * Hc;                         \
            _Pragma("unroll")                                                     \
            for (int j = 0; j < UNR; j++) {                                       \
                size_t ju = pu + (size_t)j * (3 * Hc);                            \
                size_t jx = px + (size_t)j * Hc;                                  \
                bu0[buf][j] = __half2float(U[ju]);                                \
                bu1[buf][j] = __half2float(U[ju + Hc]);                           \
                bu2[buf][j] = __half2float(U[ju + 2 * Hc]);                       \
                bxn[buf][j] = __half2float(xn[jx]);                               \
                bcn[buf][j] = __half2float(cnn[jx]);                              \
            }                                                                     \
        }

    #define COMP(buf, nb)                                                         \
        {                                                                         \
            size_t px = base_x + (size_t)(nb) * UNR * Hc;                         \
            _Pragma("unroll")                                                     \
            for (int j = 0; j < UNR; j++) {                                       \
                float u0 = bu0[buf][j], u1 = bu1[buf][j], u2 = bu2[buf][j];       \
                float xr = bxn[buf][j] * SCALE_X;                                 \
                float cnv = bcn[buf][j];                                          \
                float f = 1.0f / (1.0f + __expf(-(fmaf(c, vf, u1) + bfv)));       \
                float cn = fmaf(f, c - u0, u0);                                   \
                float r = 1.0f / (1.0f + __expf(-(fmaf(c, vr, u2) + brv)));       \
                float th = tanhf(cn);                                             \
                float ht = fmaf(r, th - xr, xr);                                  \
                blend[px + (size_t)j * Hc] = __float2half(fmaf(lam, cnv - ht, ht)); \
                c = cn;                                                           \
            }                                                                     \
        }

    PREF(0, 0);
    PREF(1, 1);
    for (int n = 0; n < NB; n += 3) {
        if (n + 2 < NB) PREF(2, n + 2);
        COMP(0, n);
        if (n + 1 < NB) {
            if (n + 3 < NB) PREF(0, n + 3);
            COMP(1, n + 1);
        }
        if (n + 2 < NB) {
            if (n + 4 < NB) PREF(1, n + 4);
            COMP(2, n + 2);
        }
    }
    #undef PREF
    #undef COMP
}

// ---------------- rmsnorm + gate + ln1 + gelu -> gated(f32), a1 fp16 ----------------
__global__ void rms_gate_ln1_kernel(const fp16* __restrict__ blend, const float* __restrict__ x,
                                    const float* __restrict__ rmsw,
                                    const float* __restrict__ ln1w, const float* __restrict__ ln1b,
                                    float* __restrict__ gated, fp16* __restrict__ a1h) {
    int t = blockIdx.x, tid = threadIdx.x;
    size_t base = (size_t)t * Hc;
    float v[4], g[4];
    float sq = 0.0f;
    #pragma unroll
    for (int i = 0; i < 4; i++) {
        v[i] = __half2float(blend[base + tid + i * 256]);
        sq += v[i] * v[i];
    }
    sq = blockReduceSum(sq);
    float rs = rsqrtf(sq * (1.0f / Hc) + 1e-6f);
    float s = 0.0f;
    #pragma unroll
    for (int i = 0; i < 4; i++) {
        int idx = tid + i * 256;
        float o = rmsw[idx] * v[i] * rs;
        g[i] = o * x[base + idx];
        gated[base + idx] = g[i];
        s += g[i];
    }
    s = blockReduceSum(s);
    float mean = s * (1.0f / Hc);
    float var = 0.0f;
    #pragma unroll
    for (int i = 0; i < 4; i++) { float d = g[i] - mean; var += d * d; }
    var = blockReduceSum(var);
    float rstd = rsqrtf(var * (1.0f / Hc) + 1e-5f);
    #pragma unroll
    for (int i = 0; i < 4; i++) {
        int idx = tid + i * 256;
        float a = geluf((g[i] - mean) * rstd * ln1w[idx] + ln1b[idx]);
        a1h[base + idx] = __float2half(a);
    }
}

// ---------------- ln2 + gelu over 2H (fp16 in) -> a2 fp16 ----------------
__global__ void ln2_gelu_kernel(const fp16* __restrict__ t1, fp16* __restrict__ a2h,
                                const float* __restrict__ w, const float* __restrict__ b) {
    int t = blockIdx.x, tid = threadIdx.x;
    const int NN = 2 * Hc;
    size_t base = (size_t)t * NN;
    float v[8];
    float s = 0.0f;
    #pragma unroll
    for (int i = 0; i < 8; i++) { v[i] = __half2float(t1[base + tid + i * 256]); s += v[i]; }
    s = blockReduceSum(s);
    float mean = s * (1.0f / NN);
    float sq = 0.0f;
    #pragma unroll
    for (int i = 0; i < 8; i++) { float d = v[i] - mean; sq += d * d; }
    sq = blockReduceSum(sq);
    float rstd = rsqrtf(sq * (1.0f / NN) + 1e-5f);
    #pragma unroll
    for (int i = 0; i < 8; i++) {
        int idx = tid + i * 256;
        float a = geluf((v[i] - mean) * rstd * w[idx] + b[idx]);
        a2h[base + idx] = __float2half(a);
    }
}

// ---------------- launch ----------------
extern "C" void kernel_launch(void* const* d_in, const int* in_sizes, int n_in,
                              void* d_out, int out_size) {
    const float* x        = (const float*)d_in[0];
    const float* conv_w   = (const float*)d_in[1];
    const float* conv_b   = (const float*)d_in[2];
    const float* sru_ln_w = (const float*)d_in[3];
    const float* sru_ln_b = (const float*)d_in[4];
    const float* sru_W    = (const float*)d_in[5];
    const float* sru_vf   = (const float*)d_in[6];
    const float* sru_vr   = (const float*)d_in[7];
    const float* sru_bf   = (const float*)d_in[8];
    const float* sru_br   = (const float*)d_in[9];
    const float* lambda_w = (const float*)d_in[10];
    const float* rms_w    = (const float*)d_in[11];
    const float* ln1_w    = (const float*)d_in[12];
    const float* ln1_b    = (const float*)d_in[13];
    const float* lin1_w   = (const float*)d_in[14];
    const float* ln2_w    = (const float*)d_in[15];
    const float* ln2_b    = (const float*)d_in[16];
    const float* lin2_w   = (const float*)d_in[17];
    const float* lin2_b   = (const float*)d_in[18];

    int Bv = in_sizes[0] / (Lc * Hc);
    int M  = Bv * Lc;

    float *gated;
    fp16 *xh, *cnnh, *xnh, *Uh, *blendh, *a1h, *t1h, *a2h, *Wc, *Wu, *W1, *W2;
    cudaGetSymbolAddress((void**)&gated, g_gated);
    cudaGetSymbolAddress((void**)&xh,     g_xh);
    cudaGetSymbolAddress((void**)&cnnh,   g_cnnh);
    cudaGetSymbolAddress((void**)&xnh,    g_xnh);
    cudaGetSymbolAddress((void**)&Uh,     g_Uh);
    cudaGetSymbolAddress((void**)&blendh, g_blendh);
    cudaGetSymbolAddress((void**)&a1h,    g_a1h);
    cudaGetSymbolAddress((void**)&t1h,    g_t1h);
    cudaGetSymbolAddress((void**)&a2h,    g_a2h);
    cudaGetSymbolAddress((void**)&Wc, g_WcT);
    cudaGetSymbolAddress((void**)&Wu, g_WuT);
    cudaGetSymbolAddress((void**)&W1, g_W1T);
    cudaGetSymbolAddress((void**)&W2, g_W2T);

    cudaFuncSetAttribute(mma_gemm<0, 0>, cudaFuncAttributeMaxDynamicSharedMemorySize, SMEM_TOT);
    cudaFuncSetAttribute(mma_gemm<0, 1>, cudaFuncAttributeMaxDynamicSharedMemorySize, SMEM_TOT);
    cudaFuncSetAttribute(mma_gemm<1, 1>, cudaFuncAttributeMaxDynamicSharedMemorySize, SMEM_TOT);

    // weight + input prep
    wconv_kernel<<<1024, 256>>>(conv_w, Wc);
    wtrans_kernel<<<dim3(3072 / 32, 1024 / 32), dim3(32, 8)>>>(sru_W, Wu, 1024, 3072);
    wtrans_kernel<<<dim3(2048 / 32, 1024 / 32), dim3(32, 8)>>>(lin1_w, W1, 1024, 2048);
    wtrans_kernel<<<dim3(1024 / 32, 2048 / 32), dim3(32, 8)>>>(lin2_w, W2, 2048, 1024);
    fcvt_kernel<<<(size_t)M * Hc / 1024, 256>>>(x, xh);

    // 1. causal conv as GEMM -> cnnh (fp16)
    mma_gemm<1, 1><<<dim3(Hc / 128, M / 128), 256, SMEM_TOT>>>(xh, Wc, cnnh, conv_b, nullptr, Hc, 4 * Hc);
    // 2. layernorm -> xnh (fp16)
    ln_kernel<<<M, 256>>>(cnnh, xnh, sru_ln_w, sru_ln_b);
    // 3. U = xn @ sru_W -> Uh (fp16)
    mma_gemm<0, 1><<<dim3(3 * Hc / 128, M / 128), 256, SMEM_TOT>>>(xnh, Wu, Uh, nullptr, nullptr, 3 * Hc, Hc);
    // 4. SRU scan + blend (fp16 out)
    scan_kernel<<<(Bv * Hc + 31) / 32, 32>>>(Uh, xnh, cnnh, blendh,
                                             sru_vf, sru_vr, sru_bf, sru_br, lambda_w, Bv);
    // 5. rmsnorm + gate + ln1 + gelu
    rms_gate_ln1_kernel<<<M, 256>>>(blendh, x, rms_w, ln1_w, ln1_b, gated, a1h);
    // 6. t1 = a1 @ lin1_w -> t1h (fp16)
    mma_gemm<0, 1><<<dim3(2 * Hc / 128, M / 128), 256, SMEM_TOT>>>(a1h, W1, t1h, nullptr, nullptr, 2 * Hc, Hc);
    // 7. a2 = gelu(ln2(t1))
    ln2_gelu_kernel<<<M, 256>>>(t1h, a2h, ln2_w, ln2_b);
    // 8. out = a2 @ lin2_w + lin2_b + gated (f32)
    mma_gemm<0, 0><<<dim3(Hc / 128, M / 128), 256, SMEM_TOT>>>(a2h, W2, (float*)d_out, lin2_b, gated, Hc, 2 * Hc);
}

// round 10
// speedup vs baseline: 1.0701x; 1.0701x over previous
#include <cuda_runtime.h>
#include <cuda_fp16.h>
#include <math.h>
#include <stdint.h>

// ---------------- problem constants ----------------
#define Hc   1024
#define Lc   4096
#define Bc   8
#define Mtok (Bc * Lc)          // 32768 tokens

typedef __half fp16;

// ---------------- scratch (device globals; no allocs allowed) ----------------
__device__ float g_gated[(size_t)Mtok * Hc];
// fp16 intermediates
__device__ fp16 g_xh[(size_t)Mtok * Hc];
__device__ fp16 g_cnnh[(size_t)Mtok * Hc];
__device__ fp16 g_xnh[(size_t)Mtok * Hc];
__device__ fp16 g_Uh[(size_t)Mtok * 3 * Hc];
__device__ fp16 g_blendh[(size_t)Mtok * Hc];
__device__ fp16 g_a1h[(size_t)Mtok * Hc];
__device__ fp16 g_t1h[(size_t)Mtok * 2 * Hc];
__device__ fp16 g_a2h[(size_t)Mtok * 2 * Hc];
// transposed fp16 weights, layout [N][K]
__device__ fp16 g_WcT[1024 * 4096];
__device__ fp16 g_WuT[3072 * 1024];
__device__ fp16 g_W1T[2048 * 1024];
__device__ fp16 g_W2T[1024 * 2048];

// ---------------- helpers ----------------
__device__ __forceinline__ float blockReduceSum(float v) {
    __shared__ float red[32];
    int lane = threadIdx.x & 31;
    int wid  = threadIdx.x >> 5;
    #pragma unroll
    for (int o = 16; o > 0; o >>= 1) v += __shfl_xor_sync(0xffffffffu, v, o);
    if (lane == 0) red[wid] = v;
    __syncthreads();
    int nw = blockDim.x >> 5;
    if (wid == 0) {
        float s = (lane < nw) ? red[lane] : 0.0f;
        #pragma unroll
        for (int o = 16; o > 0; o >>= 1) s += __shfl_xor_sync(0xffffffffu, s, o);
        if (lane == 0) red[0] = s;
    }
    __syncthreads();
    float r = red[0];
    __syncthreads();
    return r;
}

__device__ __forceinline__ float geluf(float x) {
    return 0.5f * x * (1.0f + erff(x * 0.7071067811865476f));
}

__device__ __forceinline__ uint32_t cvta_s(const void* p) {
    uint32_t a;
    asm("{ .reg .u64 t; cvta.to.shared.u64 t, %1; cvt.u32.u64 %0, t; }" : "=r"(a) : "l"(p));
    return a;
}

// ---------------- weight prep ----------------
// fp32 [K][N] row-major -> fp16 [N][K]
__global__ void wtrans_kernel(const float* __restrict__ in,
                              fp16* __restrict__ oh, int Kd, int N) {
    __shared__ float tile[32][33];
    int n0 = blockIdx.x * 32, k0 = blockIdx.y * 32;
    int tx = threadIdx.x, ty = threadIdx.y;  // 32 x 8
    #pragma unroll
    for (int i = 0; i < 32; i += 8)
        tile[ty + i][tx] = in[(size_t)(k0 + ty + i) * N + n0 + tx];
    __syncthreads();
    #pragma unroll
    for (int i = 0; i < 32; i += 8) {
        float v = tile[tx][ty + i];
        oh[(size_t)(n0 + ty + i) * Kd + k0 + tx] = __float2half(v);
    }
}

// conv weights (ho,hi,k) -> [ho][k*1024+hi]
__global__ void wconv_kernel(const float* __restrict__ w, fp16* __restrict__ oh) {
    int ho = blockIdx.x;
    for (int hi = threadIdx.x; hi < 1024; hi += 256) {
        float4 v = *reinterpret_cast<const float4*>(w + ((size_t)ho * 1024 + hi) * 4);
        float vv[4] = {v.x, v.y, v.z, v.w};
        #pragma unroll
        for (int k = 0; k < 4; k++)
            oh[(size_t)ho * 4096 + k * 1024 + hi] = __float2half(vv[k]);
    }
}

// fp32 -> fp16 elementwise
__global__ void fcvt_kernel(const float* __restrict__ in, fp16* __restrict__ oh) {
    size_t i = ((size_t)blockIdx.x * 256 + threadIdx.x) * 4;
    float4 v = *reinterpret_cast<const float4*>(in + i);
    __half2 a = __floats2half2_rn(v.x, v.y);
    __half2 b = __floats2half2_rn(v.z, v.w);
    *reinterpret_cast<__half2*>(oh + i)     = a;
    *reinterpret_cast<__half2*>(oh + i + 2) = b;
}

// ---------------- fp16 HMMA GEMM: 128x128 tile, 4 warps of 64x64, 2 CTA/SM ----------------
// C = A @ B (+bias)(+resid); A: [M][K] fp16 (CONV=1: implicit im2col of x),
// B: [N][K] fp16. F16OUT=1: C fp16 (+bias); else f32 (+bias,+resid).
#define ROWB   80                 // padded SMEM row stride: 64B data + 16B pad
#define OPB    (128 * ROWB)       // one operand region per stage = 10240 B
#define STAGEB (2 * OPB)          // A|B = 20480 B
#define NST    3
#define SMEM_TOT (NST * STAGEB)   // 61440 B

#define MMA16816(d, a, b)                                                        \
    asm volatile("mma.sync.aligned.m16n8k16.row.col.f32.f16.f16.f32 "            \
                 "{%0,%1,%2,%3},{%4,%5,%6,%7},{%8,%9},{%0,%1,%2,%3};"            \
                 : "+f"((d)[0]), "+f"((d)[1]), "+f"((d)[2]), "+f"((d)[3])        \
                 : "r"((a)[0]), "r"((a)[1]), "r"((a)[2]), "r"((a)[3]),           \
                   "r"((b)[0]), "r"((b)[1]))

#define LDSM4(r0, r1, r2, r3, addr)                                              \
    asm volatile("ldmatrix.sync.aligned.m8n8.x4.shared.b16 {%0,%1,%2,%3}, [%4];" \
                 : "=r"(r0), "=r"(r1), "=r"(r2), "=r"(r3) : "r"(addr))

#define CPA(dst, src, sz)                                                        \
    asm volatile("cp.async.cg.shared.global [%0], [%1], 16, %2;"                 \
                 :: "r"(dst), "l"(src), "r"(sz) : "memory")

#define CPA_COMMIT() asm volatile("cp.async.commit_group;" ::: "memory")
#define CPA_WAIT1()  asm volatile("cp.async.wait_group 1;" ::: "memory")

template<int CONV, int F16OUT>
__global__ void __launch_bounds__(128, 2)
mma_gemm(const fp16* __restrict__ Ah, const fp16* __restrict__ Bh,
         void* __restrict__ Cv,
         const float* __restrict__ bias, const float* __restrict__ resid,
         int N, int Kd)
{
    extern __shared__ char sm[];
    const uint32_t sb = cvta_s(sm);
    const int tid = threadIdx.x;                   // 0..127
    const int wid = tid >> 5, lid = tid & 31;
    const int wm = wid >> 1, wn = wid & 1;         // 2 x 2 grid of 64x64 warp tiles
    const int m0 = blockIdx.y * 128, n0 = blockIdx.x * 128;

    // cp.async: 128 threads cover rows {crow + p*32}, 16B chunk cc
    const int crow = tid >> 2, cc = tid & 3;       // crow 0..31

    const uint32_t aLane = (uint32_t)((lid & 15) * ROWB + (lid >> 4) * 16);
    const uint32_t bLane = (uint32_t)((((lid & 7) + ((lid >> 4) << 3)) * ROWB) +
                                      (((lid >> 3) & 1) * 16));

    float acc[4][8][4];
    #pragma unroll
    for (int i = 0; i < 4; i++)
        #pragma unroll
        for (int j = 0; j < 8; j++)
            #pragma unroll
            for (int q = 0; q < 4; q++) acc[i][j][q] = 0.0f;

    #define ISSUE(slot, kg)                                                          \
        {                                                                            \
            uint32_t dbase = sb + (uint32_t)(slot) * STAGEB;                         \
            _Pragma("unroll")                                                        \
            for (int p = 0; p < 4; ++p) {                                            \
                int r = crow + p * 32;                                               \
                uint32_t off = (uint32_t)(r * ROWB + cc * 16);                       \
                size_t bo = (size_t)(n0 + r) * Kd + (kg) + cc * 8;                   \
                CPA(dbase + OPB + off, Bh + bo, 16);                                 \
                if (CONV) {                                                          \
                    int kidx = (kg) >> 10;                                           \
                    bool ok = (((m0 + r) & (Lc - 1)) + kidx) >= 3;                   \
                    size_t ao = (size_t)(m0 + r + kidx - 3) * Hc +                   \
                                ((kg) & 1023) + cc * 8;                              \
                    const fp16* sh = ok ? Ah + ao : Ah;                              \
                    int sz = ok ? 16 : 0;                                            \
                    CPA(dbase + off, sh, sz);                                        \
                } else {                                                             \
                    size_t ao = (size_t)(m0 + r) * Kd + (kg) + cc * 8;               \
                    CPA(dbase + off, Ah + ao, 16);                                   \
                }                                                                    \
            }                                                                        \
        }

    const int T = Kd / 32;
    ISSUE(0, 0);  CPA_COMMIT();
    ISSUE(1, 32); CPA_COMMIT();

    int slot = 0;
    for (int t = 0; t < T; ++t) {
        CPA_WAIT1();
        __syncthreads();
        if (t + 2 < T) {
            int ns = slot + 2; if (ns >= NST) ns -= NST;
            ISSUE(ns, (t + 2) * 32);
        }
        CPA_COMMIT();

        const uint32_t base = sb + (uint32_t)slot * STAGEB;
        #pragma unroll
        for (int ks = 0; ks < 2; ++ks) {
            const uint32_t ko = ks * 32;
            uint32_t ah[4][4], bh[8][2];
            #pragma unroll
            for (int i = 0; i < 4; ++i) {
                uint32_t ra = base + (uint32_t)((wm * 64 + i * 16) * ROWB) + aLane + ko;
                LDSM4(ah[i][0], ah[i][1], ah[i][2], ah[i][3], ra);
            }
            #pragma unroll
            for (int jp = 0; jp < 4; ++jp) {
                uint32_t rb = base + OPB +
                              (uint32_t)((wn * 64 + jp * 16) * ROWB) + bLane + ko;
                LDSM4(bh[2 * jp][0], bh[2 * jp][1], bh[2 * jp + 1][0], bh[2 * jp + 1][1], rb);
            }
            #pragma unroll
            for (int i = 0; i < 4; ++i)
                #pragma unroll
                for (int j = 0; j < 8; ++j)
                    MMA16816(acc[i][j], ah[i], bh[j]);
        }
        ++slot; if (slot >= NST) slot = 0;
    }

    // ---- epilogue ----
    const int g = lid >> 2, t4 = lid & 3;
    float* Cf = (float*)Cv;
    fp16*  Ch = (fp16*)Cv;
    #pragma unroll
    for (int i = 0; i < 4; ++i) {
        int r0 = m0 + wm * 64 + i * 16 + g;
        #pragma unroll
        for (int j = 0; j < 8; ++j) {
            int ccl = n0 + wn * 64 + j * 8 + 2 * t4;
            float2 v0 = make_float2(acc[i][j][0], acc[i][j][1]);
            float2 v1 = make_float2(acc[i][j][2], acc[i][j][3]);
            if (bias) {
                float2 bb = *reinterpret_cast<const float2*>(bias + ccl);
                v0.x += bb.x; v0.y += bb.y; v1.x += bb.x; v1.y += bb.y;
            }
            if (F16OUT) {
                *reinterpret_cast<__half2*>(Ch + (size_t)r0 * N + ccl) =
                    __floats2half2_rn(v0.x, v0.y);
                *reinterpret_cast<__half2*>(Ch + (size_t)(r0 + 8) * N + ccl) =
                    __floats2half2_rn(v1.x, v1.y);
            } else {
                if (resid) {
                    float2 q0 = *reinterpret_cast<const float2*>(resid + (size_t)r0 * N + ccl);
                    float2 q1 = *reinterpret_cast<const float2*>(resid + (size_t)(r0 + 8) * N + ccl);
                    v0.x += q0.x; v0.y += q0.y; v1.x += q1.x; v1.y += q1.y;
                }
                *reinterpret_cast<float2*>(Cf + (size_t)r0 * N + ccl) = v0;
                *reinterpret_cast<float2*>(Cf + (size_t)(r0 + 8) * N + ccl) = v1;
            }
        }
    }
    #undef ISSUE
}

// ---------------- layernorm over H=1024, fp16 in -> fp16 out ----------------
__global__ void ln_kernel(const fp16* __restrict__ in, fp16* __restrict__ oh,
                          const float* __restrict__ w, const float* __restrict__ b) {
    int t = blockIdx.x, tid = threadIdx.x;
    const fp16* row = in + (size_t)t * Hc;
    float v[4];
    float s = 0.0f;
    #pragma unroll
    for (int i = 0; i < 4; i++) { v[i] = __half2float(row[tid + i * 256]); s += v[i]; }
    s = blockReduceSum(s);
    float mean = s * (1.0f / Hc);
    float sq = 0.0f;
    #pragma unroll
    for (int i = 0; i < 4; i++) { float d = v[i] - mean; sq += d * d; }
    sq = blockReduceSum(sq);
    float rstd = rsqrtf(sq * (1.0f / Hc) + 1e-5f);
    #pragma unroll
    for (int i = 0; i < 4; i++) {
        int idx = tid + i * 256;
        float o = (v[i] - mean) * rstd * w[idx] + b[idx];
        oh[(size_t)t * Hc + idx] = __float2half(o);
    }
}

// ---------------- SRU scan + lambda blend (register-pipelined, depth 8) ----------------
#define UNR 8
__global__ void __launch_bounds__(32)
scan_kernel(const fp16* __restrict__ U, const fp16* __restrict__ xn,
            const fp16* __restrict__ cnn, fp16* __restrict__ blend,
            const float* __restrict__ vf_, const float* __restrict__ vr_,
            const float* __restrict__ bf_, const float* __restrict__ br_,
            const float* __restrict__ lam_, int Bv) {
    int g = blockIdx.x * 32 + threadIdx.x;
    if (g >= Bv * Hc) return;
    int b = g >> 10, h = g & 1023;
    const float vf = vf_[h], vr = vr_[h], bfv = bf_[h], brv = br_[h], lam = lam_[h];
    const float SCALE_X = sqrtf(1.0f + expf(-4.0f));
    size_t iu = ((size_t)b * Lc) * (3 * Hc) + h;
    size_t ix = ((size_t)b * Lc) * Hc + h;

    float bu0[2][UNR], bu1[2][UNR], bu2[2][UNR], bxn[2][UNR], bcn[2][UNR];

    #pragma unroll
    for (int j = 0; j < UNR; j++) {
        size_t ju = iu + (size_t)j * (3 * Hc);
        size_t jx = ix + (size_t)j * Hc;
        bu0[0][j] = __half2float(U[ju]);
        bu1[0][j] = __half2float(U[ju + Hc]);
        bu2[0][j] = __half2float(U[ju + 2 * Hc]);
        bxn[0][j] = __half2float(xn[jx]);
        bcn[0][j] = __half2float(cnn[jx]);
    }

    float c = 0.0f;
    const int NB = Lc / UNR;
    for (int blk = 0; blk < NB; ++blk) {
        const int cur = blk & 1, nxt = cur ^ 1;
        if (blk + 1 < NB) {
            size_t iu2 = iu + (size_t)UNR * (3 * Hc);
            size_t ix2 = ix + (size_t)UNR * Hc;
            #pragma unroll
            for (int j = 0; j < UNR; j++) {
                size_t ju = iu2 + (size_t)j * (3 * Hc);
                size_t jx = ix2 + (size_t)j * Hc;
                bu0[nxt][j] = __half2float(U[ju]);
                bu1[nxt][j] = __half2float(U[ju + Hc]);
                bu2[nxt][j] = __half2float(U[ju + 2 * Hc]);
                bxn[nxt][j] = __half2float(xn[jx]);
                bcn[nxt][j] = __half2float(cnn[jx]);
            }
        }
        #pragma unroll
        for (int j = 0; j < UNR; j++) {
            float u0 = bu0[cur][j], u1 = bu1[cur][j], u2 = bu2[cur][j];
            float xr = bxn[cur][j] * SCALE_X;
            float cnv = bcn[cur][j];
            float f = 1.0f / (1.0f + __expf(-(fmaf(c, vf, u1) + bfv)));
            float cn = fmaf(f, c - u0, u0);
            float r = 1.0f / (1.0f + __expf(-(fmaf(c, vr, u2) + brv)));
            float th = tanhf(cn);
            float ht = fmaf(r, th - xr, xr);
            blend[ix + (size_t)j * Hc] = __float2half(fmaf(lam, cnv - ht, ht));
            c = cn;
        }
        iu += (size_t)UNR * (3 * Hc);
        ix += (size_t)UNR * Hc;
    }
}

// ---------------- rmsnorm + gate + ln1 + gelu -> gated(f32), a1 fp16 ----------------
__global__ void rms_gate_ln1_kernel(const fp16* __restrict__ blend, const float* __restrict__ x,
                                    const float* __restrict__ rmsw,
                                    const float* __restrict__ ln1w, const float* __restrict__ ln1b,
                                    float* __restrict__ gated, fp16* __restrict__ a1h) {
    int t = blockIdx.x, tid = threadIdx.x;
    size_t base = (size_t)t * Hc;
    float v[4], g[4];
    float sq = 0.0f;
    #pragma unroll
    for (int i = 0; i < 4; i++) {
        v[i] = __half2float(blend[base + tid + i * 256]);
        sq += v[i] * v[i];
    }
    sq = blockReduceSum(sq);
    float rs = rsqrtf(sq * (1.0f / Hc) + 1e-6f);
    float s = 0.0f;
    #pragma unroll
    for (int i = 0; i < 4; i++) {
        int idx = tid + i * 256;
        float o = rmsw[idx] * v[i] * rs;
        g[i] = o * x[base + idx];
        gated[base + idx] = g[i];
        s += g[i];
    }
    s = blockReduceSum(s);
    float mean = s * (1.0f / Hc);
    float var = 0.0f;
    #pragma unroll
    for (int i = 0; i < 4; i++) { float d = g[i] - mean; var += d * d; }
    var = blockReduceSum(var);
    float rstd = rsqrtf(var * (1.0f / Hc) + 1e-5f);
    #pragma unroll
    for (int i = 0; i < 4; i++) {
        int idx = tid + i * 256;
        float a = geluf((g[i] - mean) * rstd * ln1w[idx] + ln1b[idx]);
        a1h[base + idx] = __float2half(a);
    }
}

// ---------------- ln2 + gelu over 2H (fp16 in) -> a2 fp16 ----------------
__global__ void ln2_gelu_kernel(const fp16* __restrict__ t1, fp16* __restrict__ a2h,
                                const float* __restrict__ w, const float* __restrict__ b) {
    int t = blockIdx.x, tid = threadIdx.x;
    const int NN = 2 * Hc;
    size_t base = (size_t)t * NN;
    float v[8];
    float s = 0.0f;
    #pragma unroll
    for (int i = 0; i < 8; i++) { v[i] = __half2float(t1[base + tid + i * 256]); s += v[i]; }
    s = blockReduceSum(s);
    float mean = s * (1.0f / NN);
    float sq = 0.0f;
    #pragma unroll
    for (int i = 0; i < 8; i++) { float d = v[i] - mean; sq += d * d; }
    sq = blockReduceSum(sq);
    float rstd = rsqrtf(sq * (1.0f / NN) + 1e-5f);
    #pragma unroll
    for (int i = 0; i < 8; i++) {
        int idx = tid + i * 256;
        float a = geluf((v[i] - mean) * rstd * w[idx] + b[idx]);
        a2h[base + idx] = __float2half(a);
    }
}

// ---------------- launch ----------------
extern "C" void kernel_launch(void* const* d_in, const int* in_sizes, int n_in,
                              void* d_out, int out_size) {
    const float* x        = (const float*)d_in[0];
    const float* conv_w   = (const float*)d_in[1];
    const float* conv_b   = (const float*)d_in[2];
    const float* sru_ln_w = (const float*)d_in[3];
    const float* sru_ln_b = (const float*)d_in[4];
    const float* sru_W    = (const float*)d_in[5];
    const float* sru_vf   = (const float*)d_in[6];
    const float* sru_vr   = (const float*)d_in[7];
    const float* sru_bf   = (const float*)d_in[8];
    const float* sru_br   = (const float*)d_in[9];
    const float* lambda_w = (const float*)d_in[10];
    const float* rms_w    = (const float*)d_in[11];
    const float* ln1_w    = (const float*)d_in[12];
    const float* ln1_b    = (const float*)d_in[13];
    const float* lin1_w   = (const float*)d_in[14];
    const float* ln2_w    = (const float*)d_in[15];
    const float* ln2_b    = (const float*)d_in[16];
    const float* lin2_w   = (const float*)d_in[17];
    const float* lin2_b   = (const float*)d_in[18];

    int Bv = in_sizes[0] / (Lc * Hc);
    int M  = Bv * Lc;

    float *gated;
    fp16 *xh, *cnnh, *xnh, *Uh, *blendh, *a1h, *t1h, *a2h, *Wc, *Wu, *W1, *W2;
    cudaGetSymbolAddress((void**)&gated, g_gated);
    cudaGetSymbolAddress((void**)&xh,     g_xh);
    cudaGetSymbolAddress((void**)&cnnh,   g_cnnh);
    cudaGetSymbolAddress((void**)&xnh,    g_xnh);
    cudaGetSymbolAddress((void**)&Uh,     g_Uh);
    cudaGetSymbolAddress((void**)&blendh, g_blendh);
    cudaGetSymbolAddress((void**)&a1h,    g_a1h);
    cudaGetSymbolAddress((void**)&t1h,    g_t1h);
    cudaGetSymbolAddress((void**)&a2h,    g_a2h);
    cudaGetSymbolAddress((void**)&Wc, g_WcT);
    cudaGetSymbolAddress((void**)&Wu, g_WuT);
    cudaGetSymbolAddress((void**)&W1, g_W1T);
    cudaGetSymbolAddress((void**)&W2, g_W2T);

    cudaFuncSetAttribute(mma_gemm<0, 0>, cudaFuncAttributeMaxDynamicSharedMemorySize, SMEM_TOT);
    cudaFuncSetAttribute(mma_gemm<0, 1>, cudaFuncAttributeMaxDynamicSharedMemorySize, SMEM_TOT);
    cudaFuncSetAttribute(mma_gemm<1, 1>, cudaFuncAttributeMaxDynamicSharedMemorySize, SMEM_TOT);

    // weight + input prep
    wconv_kernel<<<1024, 256>>>(conv_w, Wc);
    wtrans_kernel<<<dim3(3072 / 32, 1024 / 32), dim3(32, 8)>>>(sru_W, Wu, 1024, 3072);
    wtrans_kernel<<<dim3(2048 / 32, 1024 / 32), dim3(32, 8)>>>(lin1_w, W1, 1024, 2048);
    wtrans_kernel<<<dim3(1024 / 32, 2048 / 32), dim3(32, 8)>>>(lin2_w, W2, 2048, 1024);
    fcvt_kernel<<<(size_t)M * Hc / 1024, 256>>>(x, xh);

    // 1. causal conv as GEMM -> cnnh (fp16)
    mma_gemm<1, 1><<<dim3(Hc / 128, M / 128), 128, SMEM_TOT>>>(xh, Wc, cnnh, conv_b, nullptr, Hc, 4 * Hc);
    // 2. layernorm -> xnh (fp16)
    ln_kernel<<<M, 256>>>(cnnh, xnh, sru_ln_w, sru_ln_b);
    // 3. U = xn @ sru_W -> Uh (fp16)
    mma_gemm<0, 1><<<dim3(3 * Hc / 128, M / 128), 128, SMEM_TOT>>>(xnh, Wu, Uh, nullptr, nullptr, 3 * Hc, Hc);
    // 4. SRU scan + blend (fp16 out)
    scan_kernel<<<(Bv * Hc + 31) / 32, 32>>>(Uh, xnh, cnnh, blendh,
                                             sru_vf, sru_vr, sru_bf, sru_br, lambda_w, Bv);
    // 5. rmsnorm + gate + ln1 + gelu
    rms_gate_ln1_kernel<<<M, 256>>>(blendh, x, rms_w, ln1_w, ln1_b, gated, a1h);
    // 6. t1 = a1 @ lin1_w -> t1h (fp16)
    mma_gemm<0, 1><<<dim3(2 * Hc / 128, M / 128), 128, SMEM_TOT>>>(a1h, W1, t1h, nullptr, nullptr, 2 * Hc, Hc);
    // 7. a2 = gelu(ln2(t1))
    ln2_gelu_kernel<<<M, 256>>>(t1h, a2h, ln2_w, ln2_b);
    // 8. out = a2 @ lin2_w + lin2_b + gated (f32)
    mma_gemm<0, 0><<<dim3(Hc / 128, M / 128), 128, SMEM_TOT>>>(a2h, W2, (float*)d_out, lin2_b, gated, Hc, 2 * Hc);
}